// round 6
// baseline (speedup 1.0000x reference)
#include <cuda_runtime.h>
#include <cuda_bf16.h>
#include <cstdint>
#include <math.h>

#define H      2048
#define E      64
#define KTOP   8
#define NTOK   16384
#define SEQ    4096
#define BATCH  4
#define MT     128
#define NBLK   (NTOK / MT)     // 128 CTAs
#define NCH    32              // K chunks of 64
#define GAPTH  4e-5f
#define LSTR   66              // ls row stride (floats), even -> float2 stores

// dynamic smem layout (two 48KB buffers)
#define OFF_BUF  1024
#define OA1      0
#define OA2      16384
#define OB1      32768
#define OB2      40960
#define BUF_SZ   49152
#define SMEM_BYTES (OFF_BUF + 2 * BUF_SZ)   // 99328

typedef unsigned long long ull;

__device__ float g_ssum[NBLK][E];
__device__ float g_cnt [NBLK][E];
__device__ int   g_done;

// ---------------- helpers ----------------
__device__ __forceinline__ uint32_t smem_u32(const void* p) {
    uint32_t a;
    asm("{ .reg .u64 t; cvta.to.shared.u64 t, %1; cvt.u32.u64 %0, t; }" : "=r"(a) : "l"(p));
    return a;
}
__device__ __forceinline__ uint32_t swz(uint32_t b) { return b ^ ((b >> 3) & 0x70); }

// split f0,f1 into hi bf16x2 and residual bf16x2
__device__ __forceinline__ void split2(float f0, float f1, uint32_t& hi, uint32_t& lo) {
    uint32_t h;
    asm("cvt.rn.bf16x2.f32 %0, %1, %2;" : "=r"(h) : "f"(f1), "f"(f0));
    float g0 = __uint_as_float(h << 16);
    float g1 = __uint_as_float(h & 0xFFFF0000u);
    asm("cvt.rn.bf16x2.f32 %0, %1, %2;" : "=r"(lo) : "f"(f1 - g1), "f"(f0 - g0));
    hi = h;
}
__device__ __forceinline__ void ldsm4(uint32_t* r, uint32_t addr) {
    asm volatile("ldmatrix.sync.aligned.m8n8.x4.shared.b16 {%0,%1,%2,%3}, [%4];"
        : "=r"(r[0]), "=r"(r[1]), "=r"(r[2]), "=r"(r[3]) : "r"(addr));
}
__device__ __forceinline__ void mma16816(float* d, const uint32_t* a, const uint32_t* b) {
    asm volatile("mma.sync.aligned.m16n8k16.row.col.f32.bf16.bf16.f32 "
        "{%0,%1,%2,%3}, {%4,%5,%6,%7}, {%8,%9}, {%0,%1,%2,%3};"
        : "+f"(d[0]), "+f"(d[1]), "+f"(d[2]), "+f"(d[3])
        : "r"(a[0]), "r"(a[1]), "r"(a[2]), "r"(a[3]), "r"(b[0]), "r"(b[1]));
}
// ------------------------------------------

__global__ __launch_bounds__(256, 1)
void gate_kernel(const float* __restrict__ x,
                 const float* __restrict__ w,
                 float* __restrict__ out)
{
    extern __shared__ __align__(1024) char smem[];
    __shared__ int cnt[E];
    __shared__ int nflag, flist[MT], islast;
    __shared__ float part[256];

    const uint32_t sb = smem_u32(smem);
    const int tid = threadIdx.x;
    const int wid = tid >> 5;
    const int lid = tid & 31;
    const int m0  = blockIdx.x * MT;

    if (tid == 0) nflag = 0;
    if (tid < E) cnt[tid] = 0;

    // ---------------- producer mapping ----------------
    const int xr = tid >> 1, xh = tid & 1;      // x: row 0..127, half (32 cols)
    const int wr = tid >> 2, wq = tid & 3;      // w: row 0..63, quarter (16 cols)
    const float* xrow = x + (size_t)(m0 + xr) * H + xh * 32;
    const float* wrow = w + (size_t)wr * H + wq * 16;

    uint32_t xso[8], wso[4];
#pragma unroll
    for (int i = 0; i < 8; i++) xso[i] = swz((uint32_t)(xr * 128 + xh * 64 + i * 8));
#pragma unroll
    for (int i = 0; i < 4; i++) wso[i] = swz((uint32_t)(wr * 128 + wq * 32 + i * 8));

    // ---------------- consumer mapping ----------------
    const int mbase = (wid & 3) * 32;   // token tile base
    const int nbase = (wid >> 2) * 32;  // expert tile base
    const int arow = lid & 15;          // ldmatrix A: row within m16
    const int akh  = lid >> 4;          // k-half (16B)
    const int brow = ((lid >> 4) * 8) + (lid & 7);  // ldmatrix B: 2 n8 tiles
    const int bkh  = (lid >> 3) & 1;

    float acc[2][4][4];
#pragma unroll
    for (int mi = 0; mi < 2; mi++)
#pragma unroll
        for (int t = 0; t < 4; t++)
#pragma unroll
            for (int r = 0; r < 4; r++) acc[mi][t][r] = 0.f;

    float4 xv[8], wv[4];
#pragma unroll
    for (int i = 0; i < 8; i++) xv[i] = *(const float4*)(xrow + i * 4);
#pragma unroll
    for (int i = 0; i < 4; i++) wv[i] = *(const float4*)(wrow + i * 4);

    // ---------------- mainloop: 32 chunks of K=64 ----------------
    for (int c = 0; c < NCH; c++) {
        char* buf = smem + OFF_BUF + (c & 1) * BUF_SZ;

#pragma unroll
        for (int i = 0; i < 8; i++) {
            uint32_t h0, l0, h1, l1;
            split2(xv[i].x, xv[i].y, h0, l0);
            split2(xv[i].z, xv[i].w, h1, l1);
            *(uint2*)(buf + OA1 + xso[i]) = make_uint2(h0, h1);
            *(uint2*)(buf + OA2 + xso[i]) = make_uint2(l0, l1);
        }
#pragma unroll
        for (int i = 0; i < 4; i++) {
            uint32_t h0, l0, h1, l1;
            split2(wv[i].x, wv[i].y, h0, l0);
            split2(wv[i].z, wv[i].w, h1, l1);
            *(uint2*)(buf + OB1 + wso[i]) = make_uint2(h0, h1);
            *(uint2*)(buf + OB2 + wso[i]) = make_uint2(l0, l1);
        }
        if (c + 1 < NCH) {
            const float* xp = xrow + (c + 1) * 64;
            const float* wp = wrow + (c + 1) * 64;
#pragma unroll
            for (int i = 0; i < 8; i++) xv[i] = *(const float4*)(xp + i * 4);
#pragma unroll
            for (int i = 0; i < 4; i++) wv[i] = *(const float4*)(wp + i * 4);
        }
        __syncthreads();   // one barrier per chunk (see double-buffer argument)

        const uint32_t bb = sb + OFF_BUF + (uint32_t)(c & 1) * BUF_SZ;
#pragma unroll
        for (int ks = 0; ks < 4; ks++) {
            uint32_t a1f[2][4], a2f[2][4], bf1[2][4], bf2[2][4];
#pragma unroll
            for (int mi = 0; mi < 2; mi++) {
                uint32_t off = swz((uint32_t)((mbase + mi * 16 + arow) * 128 + ks * 32 + akh * 16));
                ldsm4(a1f[mi], bb + OA1 + off);
                ldsm4(a2f[mi], bb + OA2 + off);
            }
#pragma unroll
            for (int nj = 0; nj < 2; nj++) {
                uint32_t off = swz((uint32_t)((nbase + nj * 16 + brow) * 128 + ks * 32 + bkh * 16));
                ldsm4(bf1[nj], bb + OB1 + off);
                ldsm4(bf2[nj], bb + OB2 + off);
            }
#pragma unroll
            for (int mi = 0; mi < 2; mi++)
#pragma unroll
                for (int t = 0; t < 4; t++) {
                    const uint32_t* b1 = &bf1[t >> 1][(t & 1) * 2];
                    const uint32_t* b2 = &bf2[t >> 1][(t & 1) * 2];
                    mma16816(acc[mi][t], a1f[mi], b1);   // a1*b1
                    mma16816(acc[mi][t], a2f[mi], b1);   // a2*b1
                    mma16816(acc[mi][t], a1f[mi], b2);   // a1*b2
                }
        }
    }

    // ---------------- logits regs -> smem ----------------
    float (*ls)[LSTR] = reinterpret_cast<float(*)[LSTR]>(smem + OFF_BUF);
    {
        const int r0 = lid >> 2, c0 = 2 * (lid & 3);
#pragma unroll
        for (int mi = 0; mi < 2; mi++)
#pragma unroll
            for (int t = 0; t < 4; t++) {
                const int mr = mbase + mi * 16 + r0;
                const int nc = nbase + t * 8 + c0;
                *(float2*)&ls[mr][nc]     = make_float2(acc[mi][t][0], acc[mi][t][1]);
                *(float2*)&ls[mr + 8][nc] = make_float2(acc[mi][t][2], acc[mi][t][3]);
            }
    }
    __syncthreads();

    // ---------------- per-token epilogue + flagging ----------------
    if (tid < MT) {
        float mx = -INFINITY;
#pragma unroll 8
        for (int e = 0; e < E; e++) mx = fmaxf(mx, ls[tid][e]);
        float s = 0.f;
#pragma unroll 8
        for (int e = 0; e < E; e++) {
            float v = expf(ls[tid][e] - mx);
            s += v;
            ls[tid][e] = v;
        }
        const float inv = 1.f / s;
#pragma unroll 8
        for (int e = 0; e < E; e++) ls[tid][e] *= inv;

        ull used = 0ull;
        float pw[9]; int pi[9];
#pragma unroll
        for (int k = 0; k < 9; k++) {
            float bs = -1.f; int bi = 0;
            for (int e = 0; e < E; e++) {
                if ((used >> e) & 1ull) continue;
                float v = ls[tid][e];
                if (v > bs) { bs = v; bi = e; }
            }
            used |= (1ull << bi);
            pw[k] = bs; pi[k] = bi;
        }
        float ming = 1e30f;
#pragma unroll
        for (int k = 0; k < 8; k++) ming = fminf(ming, pw[k] - pw[k + 1]);

        if (ming < GAPTH) {
            int p = atomicAdd(&nflag, 1);
            flist[p] = tid;
        } else {
            float tsum = 0.f;
#pragma unroll
            for (int k = 0; k < KTOP; k++) tsum += pw[k];
            const float invw = 1.f / (tsum + 1e-20f);
            const size_t t = (size_t)m0 + tid;
#pragma unroll
            for (int k = 0; k < KTOP; k++) {
                out[t * KTOP + k]                       = (float)pi[k];
                out[(size_t)NTOK * KTOP + t * KTOP + k] = pw[k] * invw;
                atomicAdd(&cnt[pi[k]], 1);
            }
        }
    }
    __syncthreads();

    // ---------------- exact-recompute fixup for flagged tokens ----------------
    for (int i = wid; i < nflag; i += 8) {
        const int tl = flist[i];
        float acc0 = 0.f, acc1 = 0.f;       // experts lid and lid+32, ascending-k chain
        const float* xp = x + (size_t)(m0 + tl) * H;
        const float* w0 = w + (size_t)lid * H;
        const float* w1 = w0 + (size_t)32 * H;
        for (int k = 0; k < H; k += 8) {
            float4 xa = *(const float4*)(xp + k);
            float4 xb = *(const float4*)(xp + k + 4);
            float4 a0 = *(const float4*)(w0 + k);
            float4 b0 = *(const float4*)(w0 + k + 4);
            float4 a1v = *(const float4*)(w1 + k);
            float4 b1v = *(const float4*)(w1 + k + 4);
            acc0 = fmaf(xa.x, a0.x, acc0); acc0 = fmaf(xa.y, a0.y, acc0);
            acc0 = fmaf(xa.z, a0.z, acc0); acc0 = fmaf(xa.w, a0.w, acc0);
            acc0 = fmaf(xb.x, b0.x, acc0); acc0 = fmaf(xb.y, b0.y, acc0);
            acc0 = fmaf(xb.z, b0.z, acc0); acc0 = fmaf(xb.w, b0.w, acc0);
            acc1 = fmaf(xa.x, a1v.x, acc1); acc1 = fmaf(xa.y, a1v.y, acc1);
            acc1 = fmaf(xa.z, a1v.z, acc1); acc1 = fmaf(xa.w, a1v.w, acc1);
            acc1 = fmaf(xb.x, b1v.x, acc1); acc1 = fmaf(xb.y, b1v.y, acc1);
            acc1 = fmaf(xb.z, b1v.z, acc1); acc1 = fmaf(xb.w, b1v.w, acc1);
        }
        ls[tl][lid]      = acc0;
        ls[tl][lid + 32] = acc1;
        __syncwarp();
        if (lid == 0) {
            float mx = -INFINITY;
            for (int e = 0; e < E; e++) mx = fmaxf(mx, ls[tl][e]);
            float s = 0.f;
            for (int e = 0; e < E; e++) {
                float v = expf(ls[tl][e] - mx);
                s += v;
                ls[tl][e] = v;
            }
            const float inv = 1.f / s;
            for (int e = 0; e < E; e++) ls[tl][e] *= inv;

            ull used = 0ull;
            float pw[KTOP]; int pi[KTOP];
            float tsum = 0.f;
            for (int k = 0; k < KTOP; k++) {
                float bs = -1.f; int bi = 0;
                for (int e = 0; e < E; e++) {
                    if ((used >> e) & 1ull) continue;
                    float v = ls[tl][e];
                    if (v > bs) { bs = v; bi = e; }
                }
                used |= (1ull << bi);
                pw[k] = bs; pi[k] = bi;
                tsum += bs;
            }
            const float invw = 1.f / (tsum + 1e-20f);
            const size_t t = (size_t)m0 + tl;
            for (int k = 0; k < KTOP; k++) {
                out[t * KTOP + k]                       = (float)pi[k];
                out[(size_t)NTOK * KTOP + t * KTOP + k] = pw[k] * invw;
                atomicAdd(&cnt[pi[k]], 1);
            }
        }
        __syncwarp();
    }
    __syncthreads();

    // ---------------- per-block partials ----------------
    if (tid < E) {
        float s = 0.f;
        for (int t = 0; t < MT; t++) s += ls[t][tid];
        g_ssum[blockIdx.x][tid] = s;
        g_cnt [blockIdx.x][tid] = (float)cnt[tid];
    }
    __threadfence();
    __syncthreads();
    if (tid == 0) islast = (atomicAdd(&g_done, 1) == NBLK - 1);
    __syncthreads();

    // ---------------- fused aux reduction (last block) ----------------
    if (islast) {
        __threadfence();
        const int b = tid >> 6;
        const int e = tid & 63;
        float ss = 0.f, cc = 0.f;
        const int base = b * (NBLK / BATCH);
#pragma unroll
        for (int blk = 0; blk < NBLK / BATCH; blk++) {
            ss += g_ssum[base + blk][e];
            cc += g_cnt [base + blk][e];
        }
        part[tid] = (cc * ((float)E / (float)(SEQ * KTOP))) * (ss * (1.f / (float)SEQ));
        __syncthreads();
#pragma unroll
        for (int stride = 128; stride > 0; stride >>= 1) {
            if (tid < stride) part[tid] += part[tid + stride];
            __syncthreads();
        }
        if (tid == 0) {
            out[2 * (size_t)NTOK * KTOP] = part[0] * (0.1f / (float)BATCH);
            g_done = 0;   // reset for next graph replay
        }
    }
}

extern "C" void kernel_launch(void* const* d_in, const int* in_sizes, int n_in,
                              void* d_out, int out_size)
{
    const float* x = (const float*)d_in[0];   // hidden_states [4,4096,2048]
    const float* w = (const float*)d_in[1];   // weight        [64,2048]
    float* out = (float*)d_out;

    cudaFuncSetAttribute(gate_kernel, cudaFuncAttributeMaxDynamicSharedMemorySize, SMEM_BYTES);
    gate_kernel<<<NBLK, 256, SMEM_BYTES>>>(x, w, out);
}

// round 7
// speedup vs baseline: 1.1634x; 1.1634x over previous
#include <cuda_runtime.h>
#include <cuda_bf16.h>
#include <cstdint>
#include <math.h>

#define H      2048
#define E      64
#define KTOP   8
#define NTOK   16384
#define SEQ    4096
#define BATCH  4
#define MT     64
#define NBLK   (NTOK / MT)     // 256 CTAs
#define NCH    32              // K chunks of 64
#define GAPTH  4e-5f
#define LSTR   66

// dynamic smem: two 32KB buffers
#define OFF_BUF  1024
#define OA1      0
#define OA2      8192
#define OB1      16384
#define OB2      24576
#define BUF_SZ   32768
#define SMEM_BYTES (OFF_BUF + 2 * BUF_SZ)   // 66560

typedef unsigned long long ull;

__device__ float g_ssum[NBLK][E];
__device__ float g_cnt [NBLK][E];
__device__ int   g_done;

// ---------------- helpers ----------------
__device__ __forceinline__ uint32_t smem_u32(const void* p) {
    uint32_t a;
    asm("{ .reg .u64 t; cvta.to.shared.u64 t, %1; cvt.u32.u64 %0, t; }" : "=r"(a) : "l"(p));
    return a;
}
__device__ __forceinline__ uint32_t swz(uint32_t b) { return b ^ ((b >> 3) & 0x70); }

// split f0,f1 into hi bf16x2 and residual bf16x2
__device__ __forceinline__ void split2(float f0, float f1, uint32_t& hi, uint32_t& lo) {
    uint32_t h;
    asm("cvt.rn.bf16x2.f32 %0, %1, %2;" : "=r"(h) : "f"(f1), "f"(f0));
    float g0 = __uint_as_float(h << 16);
    float g1 = __uint_as_float(h & 0xFFFF0000u);
    asm("cvt.rn.bf16x2.f32 %0, %1, %2;" : "=r"(lo) : "f"(f1 - g1), "f"(f0 - g0));
    hi = h;
}
__device__ __forceinline__ void ldsm4(uint32_t* r, uint32_t addr) {
    asm volatile("ldmatrix.sync.aligned.m8n8.x4.shared.b16 {%0,%1,%2,%3}, [%4];"
        : "=r"(r[0]), "=r"(r[1]), "=r"(r[2]), "=r"(r[3]) : "r"(addr));
}
__device__ __forceinline__ void mma16816(float* d, const uint32_t* a, const uint32_t* b) {
    asm("mma.sync.aligned.m16n8k16.row.col.f32.bf16.bf16.f32 "
        "{%0,%1,%2,%3}, {%4,%5,%6,%7}, {%8,%9}, {%0,%1,%2,%3};"
        : "+f"(d[0]), "+f"(d[1]), "+f"(d[2]), "+f"(d[3])
        : "r"(a[0]), "r"(a[1]), "r"(a[2]), "r"(a[3]), "r"(b[0]), "r"(b[1]));
}
// convert 4 floats -> 2 packed hi bf16x2 and 2 packed lo bf16x2
__device__ __forceinline__ void conv4(const float4 v, uint32_t* h, uint32_t* l) {
    split2(v.x, v.y, h[0], l[0]);
    split2(v.z, v.w, h[1], l[1]);
}
// ------------------------------------------

__global__ __launch_bounds__(256, 2)
void gate_kernel(const float* __restrict__ x,
                 const float* __restrict__ w,
                 float* __restrict__ out)
{
    extern __shared__ __align__(1024) char smem[];
    __shared__ int cnt[E];
    __shared__ int nflag, flist[MT], islast;
    __shared__ float part[256];

    const uint32_t sb = smem_u32(smem);
    const int tid = threadIdx.x;
    const int wid = tid >> 5;
    const int lid = tid & 31;
    const int m0  = blockIdx.x * MT;

    if (tid == 0) nflag = 0;
    if (tid < E) cnt[tid] = 0;

    // ---------------- producer mapping: 64x64 fp32 chunk each for x and w ----
    const int pr = tid >> 2;            // row 0..63
    const int pq = tid & 3;             // 16-col quarter
    const float* xrow = x + (size_t)(m0 + pr) * H + pq * 16;
    const float* wrow = w + (size_t)pr * H + pq * 16;
    const uint32_t sto0 = swz((uint32_t)(pr * 128 + pq * 32));       // cols 0-7
    const uint32_t sto1 = swz((uint32_t)(pr * 128 + pq * 32 + 16));  // cols 8-15

    // ---------------- consumer mapping ----------------
    const int mbase = (wid & 3) * 16;   // token tile base (m16)
    const int nbase = (wid >> 2) * 32;  // expert tile base (n32)
    const int arow = lid & 15;
    const int akh  = lid >> 4;
    const int brow = ((lid >> 4) * 8) + (lid & 7);
    const int bkh  = (lid >> 3) & 1;
    // ldsm relative addresses inside a buffer (bits 5-6 zero pre-swizzle -> XOR ks<<5)
    const uint32_t relA  = swz((uint32_t)((mbase + arow) * 128 + akh * 16));
    const uint32_t relB0 = swz((uint32_t)((nbase + brow) * 128 + bkh * 16));
    const uint32_t relB1 = swz((uint32_t)((nbase + 16 + brow) * 128 + bkh * 16));

    float acc[4][4];
#pragma unroll
    for (int t = 0; t < 4; t++)
#pragma unroll
        for (int r = 0; r < 4; r++) acc[t][r] = 0.f;

    float4 xv[4], wv[4];
#pragma unroll
    for (int i = 0; i < 4; i++) xv[i] = *(const float4*)(xrow + i * 4);
#pragma unroll
    for (int i = 0; i < 4; i++) wv[i] = *(const float4*)(wrow + i * 4);

    // ---------------- mainloop ----------------
    for (int c = 0; c < NCH; c++) {
        char* buf = smem + OFF_BUF + (c & 1) * BUF_SZ;
        {
            uint32_t h[4], l[4];
            conv4(xv[0], h, l); conv4(xv[1], h + 2, l + 2);
            *(uint4*)(buf + OA1 + sto0) = make_uint4(h[0], h[1], h[2], h[3]);
            *(uint4*)(buf + OA2 + sto0) = make_uint4(l[0], l[1], l[2], l[3]);
            conv4(xv[2], h, l); conv4(xv[3], h + 2, l + 2);
            *(uint4*)(buf + OA1 + sto1) = make_uint4(h[0], h[1], h[2], h[3]);
            *(uint4*)(buf + OA2 + sto1) = make_uint4(l[0], l[1], l[2], l[3]);
            conv4(wv[0], h, l); conv4(wv[1], h + 2, l + 2);
            *(uint4*)(buf + OB1 + sto0) = make_uint4(h[0], h[1], h[2], h[3]);
            *(uint4*)(buf + OB2 + sto0) = make_uint4(l[0], l[1], l[2], l[3]);
            conv4(wv[2], h, l); conv4(wv[3], h + 2, l + 2);
            *(uint4*)(buf + OB1 + sto1) = make_uint4(h[0], h[1], h[2], h[3]);
            *(uint4*)(buf + OB2 + sto1) = make_uint4(l[0], l[1], l[2], l[3]);
        }
        if (c + 1 < NCH) {
            const float* xp = xrow + (c + 1) * 64;
            const float* wp = wrow + (c + 1) * 64;
#pragma unroll
            for (int i = 0; i < 4; i++) xv[i] = *(const float4*)(xp + i * 4);
#pragma unroll
            for (int i = 0; i < 4; i++) wv[i] = *(const float4*)(wp + i * 4);
        }
        __syncthreads();

        const uint32_t bufb = sb + OFF_BUF + (uint32_t)(c & 1) * BUF_SZ;
#pragma unroll
        for (int ks = 0; ks < 4; ks++) {
            const uint32_t kx = (uint32_t)(ks << 5);
            uint32_t a1[4], a2[4], b1a[4], b1b[4], b2a[4], b2b[4];
            ldsm4(a1,  bufb + OA1 + (relA  ^ kx));
            ldsm4(a2,  bufb + OA2 + (relA  ^ kx));
            ldsm4(b1a, bufb + OB1 + (relB0 ^ kx));
            ldsm4(b1b, bufb + OB1 + (relB1 ^ kx));
            ldsm4(b2a, bufb + OB2 + (relB0 ^ kx));
            ldsm4(b2b, bufb + OB2 + (relB1 ^ kx));
#pragma unroll
            for (int t = 0; t < 4; t++) {
                const uint32_t* p1 = (t < 2) ? &b1a[(t & 1) * 2] : &b1b[(t & 1) * 2];
                const uint32_t* p2 = (t < 2) ? &b2a[(t & 1) * 2] : &b2b[(t & 1) * 2];
                mma16816(acc[t], a1, p1);   // a1*b1
                mma16816(acc[t], a2, p1);   // a2*b1
                mma16816(acc[t], a1, p2);   // a1*b2
            }
        }
    }

    // ---------------- logits regs -> smem ----------------
    float (*ls)[LSTR] = reinterpret_cast<float(*)[LSTR]>(smem + OFF_BUF);
    {
        const int r0 = lid >> 2, c0 = 2 * (lid & 3);
#pragma unroll
        for (int t = 0; t < 4; t++) {
            const int mr = mbase + r0;
            const int nc = nbase + t * 8 + c0;
            *(float2*)&ls[mr][nc]     = make_float2(acc[t][0], acc[t][1]);
            *(float2*)&ls[mr + 8][nc] = make_float2(acc[t][2], acc[t][3]);
        }
    }
    __syncthreads();

    // ---------------- per-token epilogue + flagging ----------------
    if (tid < MT) {
        float mx = -INFINITY;
#pragma unroll 8
        for (int e = 0; e < E; e++) mx = fmaxf(mx, ls[tid][e]);
        float s = 0.f;
#pragma unroll 8
        for (int e = 0; e < E; e++) {
            float v = expf(ls[tid][e] - mx);
            s += v;
            ls[tid][e] = v;
        }
        const float inv = 1.f / s;
#pragma unroll 8
        for (int e = 0; e < E; e++) ls[tid][e] *= inv;

        ull used = 0ull;
        float pw[9]; int pi[9];
#pragma unroll
        for (int k = 0; k < 9; k++) {
            float bs = -1.f; int bi = 0;
            for (int e = 0; e < E; e++) {
                if ((used >> e) & 1ull) continue;
                float v = ls[tid][e];
                if (v > bs) { bs = v; bi = e; }
            }
            used |= (1ull << bi);
            pw[k] = bs; pi[k] = bi;
        }
        float ming = 1e30f;
#pragma unroll
        for (int k = 0; k < 8; k++) ming = fminf(ming, pw[k] - pw[k + 1]);

        if (ming < GAPTH) {
            int p = atomicAdd(&nflag, 1);
            flist[p] = tid;
        } else {
            float tsum = 0.f;
#pragma unroll
            for (int k = 0; k < KTOP; k++) tsum += pw[k];
            const float invw = 1.f / (tsum + 1e-20f);
            const size_t t = (size_t)m0 + tid;
#pragma unroll
            for (int k = 0; k < KTOP; k++) {
                out[t * KTOP + k]                       = (float)pi[k];
                out[(size_t)NTOK * KTOP + t * KTOP + k] = pw[k] * invw;
                atomicAdd(&cnt[pi[k]], 1);
            }
        }
    }
    __syncthreads();

    // ---------------- exact-recompute fixup for flagged tokens ----------------
    for (int i = wid; i < nflag; i += 8) {
        const int tl = flist[i];
        float acc0 = 0.f, acc1 = 0.f;       // experts lid, lid+32: ascending-k chain
        const float* xp = x + (size_t)(m0 + tl) * H;
        const float* w0 = w + (size_t)lid * H;
        const float* w1 = w0 + (size_t)32 * H;
        for (int k = 0; k < H; k += 8) {
            float4 xa = *(const float4*)(xp + k);
            float4 xb = *(const float4*)(xp + k + 4);
            float4 a0 = *(const float4*)(w0 + k);
            float4 b0 = *(const float4*)(w0 + k + 4);
            float4 a1v = *(const float4*)(w1 + k);
            float4 b1v = *(const float4*)(w1 + k + 4);
            acc0 = fmaf(xa.x, a0.x, acc0); acc0 = fmaf(xa.y, a0.y, acc0);
            acc0 = fmaf(xa.z, a0.z, acc0); acc0 = fmaf(xa.w, a0.w, acc0);
            acc0 = fmaf(xb.x, b0.x, acc0); acc0 = fmaf(xb.y, b0.y, acc0);
            acc0 = fmaf(xb.z, b0.z, acc0); acc0 = fmaf(xb.w, b0.w, acc0);
            acc1 = fmaf(xa.x, a1v.x, acc1); acc1 = fmaf(xa.y, a1v.y, acc1);
            acc1 = fmaf(xa.z, a1v.z, acc1); acc1 = fmaf(xa.w, a1v.w, acc1);
            acc1 = fmaf(xb.x, b1v.x, acc1); acc1 = fmaf(xb.y, b1v.y, acc1);
            acc1 = fmaf(xb.z, b1v.z, acc1); acc1 = fmaf(xb.w, b1v.w, acc1);
        }
        ls[tl][lid]      = acc0;
        ls[tl][lid + 32] = acc1;
        __syncwarp();
        if (lid == 0) {
            float mx = -INFINITY;
            for (int e = 0; e < E; e++) mx = fmaxf(mx, ls[tl][e]);
            float s = 0.f;
            for (int e = 0; e < E; e++) {
                float v = expf(ls[tl][e] - mx);
                s += v;
                ls[tl][e] = v;
            }
            const float inv = 1.f / s;
            for (int e = 0; e < E; e++) ls[tl][e] *= inv;

            ull used = 0ull;
            float pw[KTOP]; int pi[KTOP];
            float tsum = 0.f;
            for (int k = 0; k < KTOP; k++) {
                float bs = -1.f; int bi = 0;
                for (int e = 0; e < E; e++) {
                    if ((used >> e) & 1ull) continue;
                    float v = ls[tl][e];
                    if (v > bs) { bs = v; bi = e; }
                }
                used |= (1ull << bi);
                pw[k] = bs; pi[k] = bi;
                tsum += bs;
            }
            const float invw = 1.f / (tsum + 1e-20f);
            const size_t t = (size_t)m0 + tl;
            for (int k = 0; k < KTOP; k++) {
                out[t * KTOP + k]                       = (float)pi[k];
                out[(size_t)NTOK * KTOP + t * KTOP + k] = pw[k] * invw;
                atomicAdd(&cnt[pi[k]], 1);
            }
        }
        __syncwarp();
    }
    __syncthreads();

    // ---------------- per-block partials ----------------
    if (tid < E) {
        float s = 0.f;
        for (int t = 0; t < MT; t++) s += ls[t][tid];
        g_ssum[blockIdx.x][tid] = s;
        g_cnt [blockIdx.x][tid] = (float)cnt[tid];
    }
    __threadfence();
    __syncthreads();
    if (tid == 0) islast = (atomicAdd(&g_done, 1) == NBLK - 1);
    __syncthreads();

    // ---------------- fused aux reduction (last block) ----------------
    if (islast) {
        __threadfence();
        const int b = tid >> 6;
        const int e = tid & 63;
        float ss = 0.f, cc = 0.f;
        const int base = b * (NBLK / BATCH);
#pragma unroll
        for (int blk = 0; blk < NBLK / BATCH; blk++) {
            ss += g_ssum[base + blk][e];
            cc += g_cnt [base + blk][e];
        }
        part[tid] = (cc * ((float)E / (float)(SEQ * KTOP))) * (ss * (1.f / (float)SEQ));
        __syncthreads();
#pragma unroll
        for (int stride = 128; stride > 0; stride >>= 1) {
            if (tid < stride) part[tid] += part[tid + stride];
            __syncthreads();
        }
        if (tid == 0) {
            out[2 * (size_t)NTOK * KTOP] = part[0] * (0.1f / (float)BATCH);
            g_done = 0;   // reset for next graph replay
        }
    }
}

extern "C" void kernel_launch(void* const* d_in, const int* in_sizes, int n_in,
                              void* d_out, int out_size)
{
    const float* x = (const float*)d_in[0];   // hidden_states [4,4096,2048]
    const float* w = (const float*)d_in[1];   // weight        [64,2048]
    float* out = (float*)d_out;

    cudaFuncSetAttribute(gate_kernel, cudaFuncAttributeMaxDynamicSharedMemorySize, SMEM_BYTES);
    gate_kernel<<<NBLK, 256, SMEM_BYTES>>>(x, w, out);
}

// round 10
// speedup vs baseline: 2.3057x; 1.9819x over previous
#include <cuda_runtime.h>
#include <cuda_bf16.h>
#include <cstdint>
#include <math.h>

#define H      2048
#define E      64
#define KTOP   8
#define NTOK   16384
#define SEQ    4096
#define BATCH  4
#define MT     64
#define NBLK   (NTOK / MT)     // 256 CTAs
#define NCH    32              // K chunks of 64
#define GAPTH  8e-6f
#define LSTR   66

// dynamic smem: two 32KB buffers (xhi,xlo,whi,wlo 8KB each)
#define OFF_BUF  1024
#define OA1      0
#define OA2      8192
#define OB1      16384
#define OB2      24576
#define BUF_SZ   32768
#define SMEM_BYTES (OFF_BUF + 2 * BUF_SZ)   // 66560
// fixup scratch inside buffer region (ls uses first ~17KB)
#define OFF_WST  (OFF_BUF + 20480)          // float[64][132] = 33792 B

typedef unsigned long long ull;

__device__ float    g_ssum[NBLK][E];
__device__ float    g_cnt [NBLK][E];
__device__ int      g_done;
__device__ __align__(16) uint32_t g_wimg[NCH][2][2048];   // swizzled bf16 hi/lo W images

// ---------------- helpers ----------------
__device__ __forceinline__ uint32_t smem_u32(const void* p) {
    uint32_t a;
    asm("{ .reg .u64 t; cvta.to.shared.u64 t, %1; cvt.u32.u64 %0, t; }" : "=r"(a) : "l"(p));
    return a;
}
__device__ __forceinline__ uint32_t swz(uint32_t b) { return b ^ ((b >> 3) & 0x70); }

__device__ __forceinline__ void split2(float f0, float f1, uint32_t& hi, uint32_t& lo) {
    uint32_t h;
    asm("cvt.rn.bf16x2.f32 %0, %1, %2;" : "=r"(h) : "f"(f1), "f"(f0));
    float g0 = __uint_as_float(h << 16);
    float g1 = __uint_as_float(h & 0xFFFF0000u);
    asm("cvt.rn.bf16x2.f32 %0, %1, %2;" : "=r"(lo) : "f"(f1 - g1), "f"(f0 - g0));
    hi = h;
}
__device__ __forceinline__ void ldsm4(uint32_t* r, uint32_t addr) {
    asm volatile("ldmatrix.sync.aligned.m8n8.x4.shared.b16 {%0,%1,%2,%3}, [%4];"
        : "=r"(r[0]), "=r"(r[1]), "=r"(r[2]), "=r"(r[3]) : "r"(addr));
}
__device__ __forceinline__ void mma16816(float* d, const uint32_t* a, const uint32_t* b) {
    asm("mma.sync.aligned.m16n8k16.row.col.f32.bf16.bf16.f32 "
        "{%0,%1,%2,%3}, {%4,%5,%6,%7}, {%8,%9}, {%0,%1,%2,%3};"
        : "+f"(d[0]), "+f"(d[1]), "+f"(d[2]), "+f"(d[3])
        : "r"(a[0]), "r"(a[1]), "r"(a[2]), "r"(a[3]), "r"(b[0]), "r"(b[1]));
}
__device__ __forceinline__ void conv4(const float4 v, uint32_t* h, uint32_t* l) {
    split2(v.x, v.y, h[0], l[0]);
    split2(v.z, v.w, h[1], l[1]);
}
// ------------------------------------------

// Pre-split W into chunk-local swizzled bf16 hi/lo images.
__global__ __launch_bounds__(256, 1)
void wsplit_kernel(const float* __restrict__ w)
{
    int base = (blockIdx.x * 256 + threadIdx.x) * 4;   // pair index, 4 pairs/thread
#pragma unroll
    for (int j = 0; j < 4; j++) {
        int pid = base + j;               // 0 .. 65535
        int r   = pid >> 10;              // expert row
        int kp  = pid & 1023;             // k-pair over H
        int c   = kp >> 5;                // chunk
        int kk2 = kp & 31;                // pair within chunk
        float f0 = w[(size_t)r * H + kp * 2];
        float f1 = w[(size_t)r * H + kp * 2 + 1];
        uint32_t hi, lo;
        split2(f0, f1, hi, lo);
        uint32_t off = swz((uint32_t)(r * 128 + kk2 * 4)) >> 2;
        g_wimg[c][0][off] = hi;
        g_wimg[c][1][off] = lo;
    }
}

__global__ __launch_bounds__(256, 2)
void gate_kernel(const float* __restrict__ x,
                 const float* __restrict__ w,
                 float* __restrict__ out)
{
    extern __shared__ __align__(1024) char smem[];
    __shared__ __align__(16) float xst[128];
    __shared__ __align__(16) float part[256];
    __shared__ int cnt[E];
    __shared__ int nflag, flist[MT], islast;

    const uint32_t sb = smem_u32(smem);
    const int tid = threadIdx.x;
    const int wid = tid >> 5;
    const int lid = tid & 31;
    const int m0  = blockIdx.x * MT;

    if (tid == 0) nflag = 0;
    if (tid < E) cnt[tid] = 0;

    // ---------------- producer mapping ----------------
    const int pr = tid >> 2;            // x row 0..63
    const int pq = tid & 3;             // 16-col quarter
    const float* xrow = x + (size_t)(m0 + pr) * H + pq * 16;
    const uint32_t sto0 = swz((uint32_t)(pr * 128 + pq * 32));
    const uint32_t sto1 = swz((uint32_t)(pr * 128 + pq * 32 + 16));

    // ---------------- consumer mapping ----------------
    const int mbase = (wid & 3) * 16;
    const int nbase = (wid >> 2) * 32;
    const int arow = lid & 15;
    const int akh  = lid >> 4;
    const int brow = ((lid >> 4) * 8) + (lid & 7);
    const int bkh  = (lid >> 3) & 1;
    const uint32_t relA  = swz((uint32_t)((mbase + arow) * 128 + akh * 16));
    const uint32_t relB0 = swz((uint32_t)((nbase + brow) * 128 + bkh * 16));
    const uint32_t relB1 = swz((uint32_t)((nbase + 16 + brow) * 128 + bkh * 16));

    float acc[4][4];
#pragma unroll
    for (int t = 0; t < 4; t++)
#pragma unroll
        for (int r = 0; r < 4; r++) acc[t][r] = 0.f;

    float4 xv[4];
    uint4  wv[4];
#pragma unroll
    for (int i = 0; i < 4; i++) xv[i] = *(const float4*)(xrow + i * 4);
#pragma unroll
    for (int i = 0; i < 2; i++) {
        wv[i]     = ((const uint4*)&g_wimg[0][0][0])[tid * 2 + i];
        wv[2 + i] = ((const uint4*)&g_wimg[0][1][0])[tid * 2 + i];
    }

    // ---------------- mainloop ----------------
    for (int c = 0; c < NCH; c++) {
        char* buf = smem + OFF_BUF + (c & 1) * BUF_SZ;
        {
            uint32_t h[4], l[4];
            conv4(xv[0], h, l); conv4(xv[1], h + 2, l + 2);
            *(uint4*)(buf + OA1 + sto0) = make_uint4(h[0], h[1], h[2], h[3]);
            *(uint4*)(buf + OA2 + sto0) = make_uint4(l[0], l[1], l[2], l[3]);
            conv4(xv[2], h, l); conv4(xv[3], h + 2, l + 2);
            *(uint4*)(buf + OA1 + sto1) = make_uint4(h[0], h[1], h[2], h[3]);
            *(uint4*)(buf + OA2 + sto1) = make_uint4(l[0], l[1], l[2], l[3]);
            // W pass-through (already split bf16, image is pre-swizzled)
            *(uint4*)(buf + OB1 + tid * 32)      = wv[0];
            *(uint4*)(buf + OB1 + tid * 32 + 16) = wv[1];
            *(uint4*)(buf + OB2 + tid * 32)      = wv[2];
            *(uint4*)(buf + OB2 + tid * 32 + 16) = wv[3];
        }
        if (c + 1 < NCH) {
            const float* xp = xrow + (c + 1) * 64;
#pragma unroll
            for (int i = 0; i < 4; i++) xv[i] = *(const float4*)(xp + i * 4);
#pragma unroll
            for (int i = 0; i < 2; i++) {
                wv[i]     = ((const uint4*)&g_wimg[c + 1][0][0])[tid * 2 + i];
                wv[2 + i] = ((const uint4*)&g_wimg[c + 1][1][0])[tid * 2 + i];
            }
        }
        __syncthreads();

        const uint32_t bufb = sb + OFF_BUF + (uint32_t)(c & 1) * BUF_SZ;
#pragma unroll
        for (int ks = 0; ks < 4; ks++) {
            const uint32_t kx = (uint32_t)(ks << 5);
            uint32_t a1[4], a2[4], b1a[4], b1b[4], b2a[4], b2b[4];
            ldsm4(a1,  bufb + OA1 + (relA  ^ kx));
            ldsm4(a2,  bufb + OA2 + (relA  ^ kx));
            ldsm4(b1a, bufb + OB1 + (relB0 ^ kx));
            ldsm4(b1b, bufb + OB1 + (relB1 ^ kx));
            ldsm4(b2a, bufb + OB2 + (relB0 ^ kx));
            ldsm4(b2b, bufb + OB2 + (relB1 ^ kx));
#pragma unroll
            for (int t = 0; t < 4; t++) {
                const uint32_t* p1 = (t < 2) ? &b1a[(t & 1) * 2] : &b1b[(t & 1) * 2];
                const uint32_t* p2 = (t < 2) ? &b2a[(t & 1) * 2] : &b2b[(t & 1) * 2];
                mma16816(acc[t], a1, p1);
                mma16816(acc[t], a2, p1);
                mma16816(acc[t], a1, p2);
            }
        }
    }

    // ---------------- logits regs -> smem ----------------
    float (*ls)[LSTR] = reinterpret_cast<float(*)[LSTR]>(smem + OFF_BUF);
    {
        const int r0 = lid >> 2, c0 = 2 * (lid & 3);
#pragma unroll
        for (int t = 0; t < 4; t++) {
            const int mr = mbase + r0;
            const int nc = nbase + t * 8 + c0;
            *(float2*)&ls[mr][nc]     = make_float2(acc[t][0], acc[t][1]);
            *(float2*)&ls[mr + 8][nc] = make_float2(acc[t][2], acc[t][3]);
        }
    }
    __syncthreads();

    // ---------------- per-token epilogue + flagging ----------------
    if (tid < MT) {
        float mx = -INFINITY;
#pragma unroll 8
        for (int e = 0; e < E; e++) mx = fmaxf(mx, ls[tid][e]);
        float s = 0.f;
#pragma unroll 8
        for (int e = 0; e < E; e++) {
            float v = expf(ls[tid][e] - mx);
            s += v;
            ls[tid][e] = v;
        }
        const float inv = 1.f / s;
#pragma unroll 8
        for (int e = 0; e < E; e++) ls[tid][e] *= inv;

        ull used = 0ull;
        float pw[9]; int pi[9];
#pragma unroll
        for (int k = 0; k < 9; k++) {
            float bs = -1.f; int bi = 0;
            for (int e = 0; e < E; e++) {
                if ((used >> e) & 1ull) continue;
                float v = ls[tid][e];
                if (v > bs) { bs = v; bi = e; }
            }
            used |= (1ull << bi);
            pw[k] = bs; pi[k] = bi;
        }
        float ming = 1e30f;
#pragma unroll
        for (int k = 0; k < 8; k++) ming = fminf(ming, pw[k] - pw[k + 1]);

        if (ming < GAPTH) {
            int p = atomicAdd(&nflag, 1);
            flist[p] = tid;
        } else {
            float tsum = 0.f;
#pragma unroll
            for (int k = 0; k < KTOP; k++) tsum += pw[k];
            const float invw = 1.f / (tsum + 1e-20f);
            const size_t t = (size_t)m0 + tid;
#pragma unroll
            for (int k = 0; k < KTOP; k++) {
                out[t * KTOP + k]                       = (float)pi[k];
                out[(size_t)NTOK * KTOP + t * KTOP + k] = pw[k] * invw;
                atomicAdd(&cnt[pi[k]], 1);
            }
        }
    }
    __syncthreads();

    // ---------------- block-cooperative exact fixup ----------------
    float (*wst)[132] = reinterpret_cast<float(*)[132]>(smem + OFF_WST);
    const int fe = tid >> 2, fl = tid & 3;
    for (int f = 0; f < nflag; f++) {
        const int tl = flist[f];
        float accf = 0.f;
        for (int kb = 0; kb < H; kb += 128) {
            const float* wsrc = w + (size_t)fe * H + kb;
#pragma unroll
            for (int j = 0; j < 8; j++) {
                int s4 = j * 4 + fl;
                float4 v = *(const float4*)(wsrc + s4 * 4);
                *(float4*)&wst[fe][s4 * 4] = v;
            }
            if (tid >= 64 && tid < 96) {
                float4 v = *(const float4*)(x + (size_t)(m0 + tl) * H + kb + (tid - 64) * 4);
                *(float4*)&xst[(tid - 64) * 4] = v;
            }
            __syncthreads();
            if (tid < E) {
#pragma unroll 8
                for (int kk = 0; kk < 128; kk++)
                    accf = fmaf(xst[kk], wst[tid][kk], accf);
            }
            __syncthreads();
        }
        if (tid < E) ls[tl][tid] = accf;
        __syncthreads();
        if (tid == 0) {
            float mx = -INFINITY;
            for (int e = 0; e < E; e++) mx = fmaxf(mx, ls[tl][e]);
            float s = 0.f;
            for (int e = 0; e < E; e++) {
                float v = expf(ls[tl][e] - mx);
                s += v;
                ls[tl][e] = v;
            }
            const float inv = 1.f / s;
            for (int e = 0; e < E; e++) ls[tl][e] *= inv;

            ull used = 0ull;
            float pw[KTOP]; int pi[KTOP];
            float tsum = 0.f;
            for (int k = 0; k < KTOP; k++) {
                float bs = -1.f; int bi = 0;
                for (int e = 0; e < E; e++) {
                    if ((used >> e) & 1ull) continue;
                    float v = ls[tl][e];
                    if (v > bs) { bs = v; bi = e; }
                }
                used |= (1ull << bi);
                pw[k] = bs; pi[k] = bi;
                tsum += bs;
            }
            const float invw = 1.f / (tsum + 1e-20f);
            const size_t t = (size_t)m0 + tl;
            for (int k = 0; k < KTOP; k++) {
                out[t * KTOP + k]                       = (float)pi[k];
                out[(size_t)NTOK * KTOP + t * KTOP + k] = pw[k] * invw;
                atomicAdd(&cnt[pi[k]], 1);
            }
        }
    }
    __syncthreads();

    // ---------------- per-block partials ----------------
    if (tid < E) {
        float s = 0.f;
        for (int t = 0; t < MT; t++) s += ls[t][tid];
        g_ssum[blockIdx.x][tid] = s;
        g_cnt [blockIdx.x][tid] = (float)cnt[tid];
    }
    __threadfence();
    __syncthreads();
    if (tid == 0) islast = (atomicAdd(&g_done, 1) == NBLK - 1);
    __syncthreads();

    // ---------------- fused aux reduction (last block) ----------------
    if (islast) {
        __threadfence();
        const int b = tid >> 6;
        const int e = tid & 63;
        float ss = 0.f, cc = 0.f;
        const int base = b * (NBLK / BATCH);
#pragma unroll
        for (int blk = 0; blk < NBLK / BATCH; blk++) {
            ss += g_ssum[base + blk][e];
            cc += g_cnt [base + blk][e];
        }
        part[tid] = (cc * ((float)E / (float)(SEQ * KTOP))) * (ss * (1.f / (float)SEQ));
        __syncthreads();
#pragma unroll
        for (int stride = 128; stride > 0; stride >>= 1) {
            if (tid < stride) part[tid] += part[tid + stride];
            __syncthreads();
        }
        if (tid == 0) {
            out[2 * (size_t)NTOK * KTOP] = part[0] * (0.1f / (float)BATCH);
            g_done = 0;
        }
    }
}

extern "C" void kernel_launch(void* const* d_in, const int* in_sizes, int n_in,
                              void* d_out, int out_size)
{
    const float* x = (const float*)d_in[0];   // hidden_states [4,4096,2048]
    const float* w = (const float*)d_in[1];   // weight        [64,2048]
    float* out = (float*)d_out;

    wsplit_kernel<<<64, 256>>>(w);
    cudaFuncSetAttribute(gate_kernel, cudaFuncAttributeMaxDynamicSharedMemorySize, SMEM_BYTES);
    gate_kernel<<<NBLK, 256, SMEM_BYTES>>>(x, w, out);
}